// round 3
// baseline (speedup 1.0000x reference)
#include <cuda_runtime.h>
#include <cstdint>

#define BB 512
#define TT 1024
#define ORDER 128
#define HH 1024
#define CC 10
#define NROWS (BB*TT)   // 524288

// ---- device scratch (module-load allocations, not runtime allocs) ----
__device__ unsigned g_se_bits[(size_t)NROWS * 8];    // 16 MB encoder spikes
__device__ unsigned g_sh_bits[(size_t)NROWS * 32];   // 64 MB hidden spikes
__device__ float    g_I1[(size_t)NROWS * HH];        // 2 GB hidden currents
__device__ float    g_I2[(size_t)NROWS * CC];        // 21 MB output currents
__device__ unsigned g_Bq1[4 * 64 * HH];              // hidden W digits [p][kq][n]
__device__ unsigned g_Bq2[4 * 256 * 16];             // output W digits [p][kq][n]
__device__ float    g_cmb1[HH], g_qf1[HH];
__device__ float    g_cmb2[16], g_qf2[16];

__device__ __forceinline__ unsigned smaddr(const void* p) {
    return (unsigned)__cvta_generic_to_shared(p);
}
__device__ __forceinline__ unsigned lds32(unsigned a) {
    unsigned v; asm volatile("ld.shared.b32 %0, [%1];" : "=r"(v) : "r"(a)); return v;
}
__device__ __forceinline__ void ldmx4(unsigned a[4], unsigned addr) {
    asm volatile("ldmatrix.sync.aligned.m8n8.x4.shared.b16 {%0,%1,%2,%3}, [%4];"
                 : "=r"(a[0]), "=r"(a[1]), "=r"(a[2]), "=r"(a[3]) : "r"(addr));
}
__device__ __forceinline__ void imma16832(int c[4], const unsigned a[4],
                                          unsigned b0, unsigned b1) {
    asm volatile(
        "mma.sync.aligned.m16n8k32.row.col.s32.s8.s8.s32 "
        "{%0,%1,%2,%3}, {%4,%5,%6,%7}, {%8,%9}, {%0,%1,%2,%3};"
        : "+r"(c[0]), "+r"(c[1]), "+r"(c[2]), "+r"(c[3])
        : "r"(a[0]), "r"(a[1]), "r"(a[2]), "r"(a[3]), "r"(b0), "r"(b1));
}
// 4 spike bits -> 4 s8 bytes {0,1}
__device__ __forceinline__ unsigned expand4(unsigned b) {
    return (b & 1u) | ((b & 2u) << 7) | ((b & 4u) << 14) | ((b & 8u) << 21);
}

// ---------------------------------------------------------------------------
// scales: per-output-column pow2 scale so |w|/scale < 1
// ---------------------------------------------------------------------------
__global__ void k_scale1(const float* __restrict__ Wh) {
    int n = blockIdx.x * blockDim.x + threadIdx.x;   // 0..1023
    float m = 0.f;
    for (int k = 0; k < 256; k++) m = fmaxf(m, fabsf(Wh[k * HH + n]));
    int e = (m > 0.f) ? (ilogbf(m) + 1) : 0;
    g_qf1[n]  = ldexpf(1.f, 30 - e);
    g_cmb1[n] = ldexpf(1.f, e - 30);
}
__global__ void k_scale2(const float* __restrict__ Wo) {
    int n = threadIdx.x;
    if (n >= 16) return;
    float m = 0.f;
    if (n < CC) for (int k = 0; k < HH; k++) m = fmaxf(m, fabsf(Wo[k * CC + n]));
    int e = (m > 0.f) ? (ilogbf(m) + 1) : 0;
    g_qf2[n]  = ldexpf(1.f, 30 - e);
    g_cmb2[n] = ldexpf(1.f, e - 30);
}

__device__ __forceinline__ void quant_digits(float w, float qf, int d[4]) {
    int q = __float2int_rn(w * qf);   // |q| <= 2^30, w*qf exact (pow2 scale)
#pragma unroll
    for (int i = 0; i < 4; i++) {     // balanced signed base-256 digits
        int di = ((q + 128) & 255) - 128;
        d[i] = di; q = (q - di) >> 8;
    }
}

__global__ void k_quant1(const float* __restrict__ Wh) {
    int gid = blockIdx.x * blockDim.x + threadIdx.x;  // 65536 = 64kq * 1024n
    int kq = gid >> 10, n = gid & 1023;
    float qf = g_qf1[n];
    unsigned wp[4] = {0, 0, 0, 0};
#pragma unroll
    for (int j = 0; j < 4; j++) {
        int d[4]; quant_digits(Wh[(4 * kq + j) * HH + n], qf, d);
#pragma unroll
        for (int p = 0; p < 4; p++) wp[p] |= ((unsigned)d[p] & 255u) << (8 * j);
    }
#pragma unroll
    for (int p = 0; p < 4; p++) g_Bq1[(p * 64 + kq) * HH + n] = wp[p];
}

__global__ void k_quant2(const float* __restrict__ Wo) {
    int gid = blockIdx.x * blockDim.x + threadIdx.x;  // 4096 = 256kq * 16n
    int kq = gid >> 4, n = gid & 15;
    float qf = g_qf2[n];
    unsigned wp[4] = {0, 0, 0, 0};
#pragma unroll
    for (int j = 0; j < 4; j++) {
        float w = (n < CC) ? Wo[(4 * kq + j) * CC + n] : 0.f;
        int d[4]; quant_digits(w, qf, d);
#pragma unroll
        for (int p = 0; p < 4; p++) wp[p] |= ((unsigned)d[p] & 255u) << (8 * j);
    }
#pragma unroll
    for (int p = 0; p < 4; p++) g_Bq2[(p * 256 + kq) * 16 + n] = wp[p];
}

// ---------------------------------------------------------------------------
// encoder: IF neuron, soft reset; exact fp32 matching reference op order.
// ---------------------------------------------------------------------------
__global__ void __launch_bounds__(128, 8) k_encoder(const float* __restrict__ x) {
    int b = blockIdx.x, j = threadIdx.x;
    const float* xp = x + (size_t)b * TT * ORDER + j;
    unsigned* wp = g_se_bits + (size_t)b * TT * 8 + (j >> 5);
    float vp = 0.f, vn = 0.f;
    for (int t = 0; t < TT; t++) {
        float val = xp[(size_t)t * ORDER];
        vp = __fadd_rn(vp, fmaxf(val, 0.f));
        bool sp = (vp >= 1.0f);
        unsigned mp = __ballot_sync(0xffffffffu, sp);
        if (sp) vp = __fsub_rn(vp, 1.0f);
        vn = __fadd_rn(vn, fmaxf(-val, 0.f));
        bool sn = (vn >= 1.0f);
        unsigned mn = __ballot_sync(0xffffffffu, sn);
        if (sn) vn = __fsub_rn(vn, 1.0f);
        if ((j & 31) == 0) { wp[t * 8] = mp; wp[t * 8 + 4] = mn; }
    }
}

// ---------------------------------------------------------------------------
// GEMM1 (exact): I1 = bits @ W_hdn. 4 int8 limb planes, int32 exact accum,
// single fp32 rounding at recombine. CTA: 64 n-cols x (8 consecutive 128-row
// m-tiles). 8 warps = 4(wm) x 2(wn), warp tile 32m x 32n.
// ---------------------------------------------------------------------------
#define SMEM1 (34816 + 73728 + 256)
__global__ void __launch_bounds__(256, 1) k_gemm1() {
    extern __shared__ unsigned sm[];
    unsigned* smA = sm;            // A s8: 128 rows x 272B = 8704 words
    unsigned* smB = sm + 8704;     // B: 4p x 64kq x (72-stride, 64 n) words
    float* smC = (float*)(sm + 8704 + 18432);

    const int tid = threadIdx.x, lane = tid & 31, warp = tid >> 5;
    const int ntile = blockIdx.x, mg = blockIdx.y;
    const int wm = warp & 3, wn = warp >> 2;

    for (int i = tid; i < 16384; i += 256) {
        int p = i >> 12, kq = (i >> 6) & 63, n = i & 63;
        smB[p * 4608 + kq * 72 + n] = g_Bq1[(p * 64 + kq) * HH + ntile * 64 + n];
    }
    if (tid < 64) smC[tid] = g_cmb1[ntile * 64 + tid];

    const unsigned Aaddr0 = smaddr(smA)
        + (wm * 32 + (lane & 7) + ((lane >> 3) & 1) * 8) * 272 + (lane >> 4) * 16;
    const unsigned Bsm = smaddr(smB);

    for (int mt = 0; mt < 8; mt++) {
        const int mbase = (mg * 8 + mt) * 128;
        __syncthreads();
        // build A (s8 {0,1}) from spike bits
        for (int idx = tid; idx < 1024; idx += 256) {
            int r = idx >> 3, g = idx & 7;
            unsigned bits = g_se_bits[(size_t)(mbase + r) * 8 + g];
            char* dst = (char*)smA + r * 272 + g * 32;
            uint4 u;
            u.x = expand4(bits);       u.y = expand4(bits >> 4);
            u.z = expand4(bits >> 8);  u.w = expand4(bits >> 12);
            *(uint4*)dst = u;
            u.x = expand4(bits >> 16); u.y = expand4(bits >> 20);
            u.z = expand4(bits >> 24); u.w = expand4(bits >> 28);
            *(uint4*)(dst + 16) = u;
        }
        __syncthreads();

        int acc[4][2][4][4];
#pragma unroll
        for (int p = 0; p < 4; p++)
#pragma unroll
            for (int mf = 0; mf < 2; mf++)
#pragma unroll
                for (int nf = 0; nf < 4; nf++)
#pragma unroll
                    for (int r = 0; r < 4; r++) acc[p][mf][nf][r] = 0;

#pragma unroll
        for (int ks = 0; ks < 8; ks++) {
            unsigned a0[4], a1[4];
            ldmx4(a0, Aaddr0 + ks * 32);
            ldmx4(a1, Aaddr0 + 16 * 272 + ks * 32);
#pragma unroll
            for (int p = 0; p < 4; p++) {
                unsigned ba = Bsm
                    + (p * 4608 + (ks * 8 + (lane & 3)) * 72 + wn * 32 + (lane >> 2)) * 4;
#pragma unroll
                for (int nf = 0; nf < 4; nf++) {
                    unsigned b0 = lds32(ba + nf * 32);
                    unsigned b1 = lds32(ba + 1152 + nf * 32);  // kq+4 -> +4*72 words
                    imma16832(acc[p][0][nf], a0, b0, b1);
                    imma16832(acc[p][1][nf], a1, b0, b1);
                }
            }
        }

        // recombine limbs (one fp32 rounding) and store
#pragma unroll
        for (int mf = 0; mf < 2; mf++) {
            int r = mbase + wm * 32 + mf * 16 + (lane >> 2);
#pragma unroll
            for (int nf = 0; nf < 4; nf++) {
                int cl = wn * 32 + nf * 8 + (lane & 3) * 2;
                float c0 = smC[cl], c1 = smC[cl + 1];
                float v0 = ((float)(acc[0][mf][nf][0] + (acc[1][mf][nf][0] << 8))
                    + 65536.f * (float)(acc[2][mf][nf][0] + (acc[3][mf][nf][0] << 8))) * c0;
                float v1 = ((float)(acc[0][mf][nf][1] + (acc[1][mf][nf][1] << 8))
                    + 65536.f * (float)(acc[2][mf][nf][1] + (acc[3][mf][nf][1] << 8))) * c1;
                float v2 = ((float)(acc[0][mf][nf][2] + (acc[1][mf][nf][2] << 8))
                    + 65536.f * (float)(acc[2][mf][nf][2] + (acc[3][mf][nf][2] << 8))) * c0;
                float v3 = ((float)(acc[0][mf][nf][3] + (acc[1][mf][nf][3] << 8))
                    + 65536.f * (float)(acc[2][mf][nf][3] + (acc[3][mf][nf][3] << 8))) * c1;
                int cN = ntile * 64 + cl;
                *(float2*)(g_I1 + (size_t)r * HH + cN) = make_float2(v0, v1);
                *(float2*)(g_I1 + (size_t)(r + 8) * HH + cN) = make_float2(v2, v3);
            }
        }
    }
}

// ---------------------------------------------------------------------------
// scan1: LIF over T per (b,h); bitpack hidden spikes.
// ---------------------------------------------------------------------------
__global__ void __launch_bounds__(256) k_scan1() {
    int b = blockIdx.x;
    int h = blockIdx.y * 256 + threadIdx.x;
    const float* p = g_I1 + (size_t)b * TT * HH + h;
    unsigned* ow = g_sh_bits + (size_t)b * TT * 32 + (blockIdx.y * 8 + (threadIdx.x >> 5));
    float v = 0.f;
#pragma unroll 4
    for (int t = 0; t < TT; t++) {
        float I = p[(size_t)t << 10];
        v = __fadd_rn(__fmul_rn(0.9f, v), I);
        bool s = (v >= 1.0f);
        unsigned m = __ballot_sync(0xffffffffu, s);
        if (s) v = __fsub_rn(v, 1.0f);
        if ((threadIdx.x & 31) == 0) ow[t * 32] = m;
    }
}

// ---------------------------------------------------------------------------
// GEMM2 (exact int8 limbs): I2 = s_h @ W_otp, N padded to 16. CTA = 128 rows.
// ---------------------------------------------------------------------------
#define SMEM2 (98304 + 16896 + 64)
__global__ void __launch_bounds__(256, 1) k_gemm2() {
    extern __shared__ unsigned sm[];
    unsigned* smB = sm;            // 4p x 256kq x (24-stride, 16 n) words
    unsigned* smb = sm + 24576;    // 128 rows x 33 words spike bits
    float* smC = (float*)(sm + 24576 + 4224);

    const int tid = threadIdx.x, lane = tid & 31, warp = tid >> 5;
    const int mbase = blockIdx.x * 128;

    for (int i = tid; i < 16384; i += 256) {
        int p = i >> 12, kq = (i >> 4) & 255, n = i & 15;
        smB[(p * 256 + kq) * 24 + n] = g_Bq2[i];
    }
    for (int i = tid; i < 4096; i += 256)
        smb[(i >> 5) * 33 + (i & 31)] = g_sh_bits[(size_t)(mbase + (i >> 5)) * 32 + (i & 31)];
    if (tid < 16) smC[tid] = g_cmb2[tid];
    __syncthreads();

    int acc[4][2][4];
#pragma unroll
    for (int p = 0; p < 4; p++)
#pragma unroll
        for (int nf = 0; nf < 2; nf++)
#pragma unroll
            for (int r = 0; r < 4; r++) acc[p][nf][r] = 0;

    const int r0 = warp * 16 + (lane >> 2);
    const int sh = 4 * (lane & 3);
    const unsigned Bsm = smaddr(smB);

#pragma unroll 4
    for (int ks = 0; ks < 32; ks++) {
        unsigned w0 = smb[r0 * 33 + ks];
        unsigned w1 = smb[(r0 + 8) * 33 + ks];
        unsigned a[4];
        a[0] = expand4(w0 >> sh);
        a[1] = expand4(w1 >> sh);
        a[2] = expand4(w0 >> (16 + sh));
        a[3] = expand4(w1 >> (16 + sh));
#pragma unroll
        for (int p = 0; p < 4; p++) {
            unsigned ba = Bsm + ((p * 256 + ks * 8 + (lane & 3)) * 24 + (lane >> 2)) * 4;
#pragma unroll
            for (int nf = 0; nf < 2; nf++) {
                unsigned b0 = lds32(ba + nf * 32);
                unsigned b1 = lds32(ba + 384 + nf * 32);   // kq+4 -> +4*24 words
                imma16832(acc[p][nf], a, b0, b1);
            }
        }
    }

    int row = mbase + r0;
#pragma unroll
    for (int nf = 0; nf < 2; nf++) {
        int cl = nf * 8 + (lane & 3) * 2;
        if (cl < CC) {
            float c0 = smC[cl], c1 = smC[cl + 1];
            float v0 = ((float)(acc[0][nf][0] + (acc[1][nf][0] << 8))
                + 65536.f * (float)(acc[2][nf][0] + (acc[3][nf][0] << 8))) * c0;
            float v1 = ((float)(acc[0][nf][1] + (acc[1][nf][1] << 8))
                + 65536.f * (float)(acc[2][nf][1] + (acc[3][nf][1] << 8))) * c1;
            float v2 = ((float)(acc[0][nf][2] + (acc[1][nf][2] << 8))
                + 65536.f * (float)(acc[2][nf][2] + (acc[3][nf][2] << 8))) * c0;
            float v3 = ((float)(acc[0][nf][3] + (acc[1][nf][3] << 8))
                + 65536.f * (float)(acc[2][nf][3] + (acc[3][nf][3] << 8))) * c1;
            *(float2*)(g_I2 + (size_t)row * CC + cl) = make_float2(v0, v1);
            *(float2*)(g_I2 + (size_t)(row + 8) * CC + cl) = make_float2(v2, v3);
        }
    }
}

// ---------------------------------------------------------------------------
// scan2: leaky integrator per (b,c); emits membrane potential each step.
// ---------------------------------------------------------------------------
__global__ void k_scan2(float* __restrict__ out) {
    int b = blockIdx.x, c = threadIdx.x;
    if (c >= CC) return;
    const float* p = g_I2 + (size_t)b * TT * CC + c;
    float* q = out + (size_t)b * TT * CC + c;
    float v = 0.f;
#pragma unroll 4
    for (int t = 0; t < TT; t++) {
        v = __fadd_rn(__fmul_rn(0.9f, v), p[(size_t)t * CC]);
        q[(size_t)t * CC] = v;
    }
}

// ---------------------------------------------------------------------------
extern "C" void kernel_launch(void* const* d_in, const int* in_sizes, int n_in,
                              void* d_out, int out_size) {
    const float* x  = (const float*)d_in[0];
    const float* Wh = (const float*)d_in[1];
    const float* Wo = (const float*)d_in[2];
    float* out = (float*)d_out;

    cudaFuncSetAttribute(k_gemm1, cudaFuncAttributeMaxDynamicSharedMemorySize, SMEM1);
    cudaFuncSetAttribute(k_gemm2, cudaFuncAttributeMaxDynamicSharedMemorySize, SMEM2);

    k_scale1<<<4, 256>>>(Wh);
    k_scale2<<<1, 32>>>(Wo);
    k_quant1<<<256, 256>>>(Wh);
    k_quant2<<<16, 256>>>(Wo);
    k_encoder<<<BB, 128>>>(x);
    k_gemm1<<<dim3(16, 512), 256, SMEM1>>>();
    k_scan1<<<dim3(BB, 4), 256>>>();
    k_gemm2<<<4096, 256, SMEM2>>>();
    k_scan2<<<BB, 32>>>(out);
}

// round 5
// speedup vs baseline: 1.2479x; 1.2479x over previous
#include <cuda_runtime.h>
#include <cstdint>

#define BB 512
#define TT 1024
#define ORDER 128
#define HH 1024
#define CC 10
#define NROWS (BB*TT)   // 524288

// ---- device scratch (module-load, not runtime allocs) ----
__device__ unsigned g_se_bits[(size_t)NROWS * 8];    // 16 MB encoder spikes
__device__ unsigned g_sh_bits[(size_t)NROWS * 32];   // 64 MB hidden spikes
__device__ float    g_I2[(size_t)NROWS * CC];        // 21 MB output currents
__device__ unsigned g_Bq1[3 * 64 * HH];              // hidden W digits [p][kq][h] (23-bit)
__device__ unsigned g_Bq2[4 * 256 * 16];             // output W digits [p][kq][n] (30-bit)
__device__ float    g_cmb1[HH], g_qf1[HH];
__device__ float    g_cmb2[16], g_qf2[16];

__device__ __forceinline__ unsigned smaddr(const void* p) {
    return (unsigned)__cvta_generic_to_shared(p);
}
__device__ __forceinline__ unsigned lds32(unsigned a) {
    unsigned v; asm volatile("ld.shared.b32 %0, [%1];" : "=r"(v) : "r"(a)); return v;
}
__device__ __forceinline__ void ldmx4(unsigned a[4], unsigned addr) {
    asm volatile("ldmatrix.sync.aligned.m8n8.x4.shared.b16 {%0,%1,%2,%3}, [%4];"
                 : "=r"(a[0]), "=r"(a[1]), "=r"(a[2]), "=r"(a[3]) : "r"(addr));
}
__device__ __forceinline__ void imma16832(int c[4], const unsigned a[4],
                                          unsigned b0, unsigned b1) {
    asm volatile(
        "mma.sync.aligned.m16n8k32.row.col.s32.s8.s8.s32 "
        "{%0,%1,%2,%3}, {%4,%5,%6,%7}, {%8,%9}, {%0,%1,%2,%3};"
        : "+r"(c[0]), "+r"(c[1]), "+r"(c[2]), "+r"(c[3])
        : "r"(a[0]), "r"(a[1]), "r"(a[2]), "r"(a[3]), "r"(b0), "r"(b1));
}
// 4 spike bits -> 4 s8 bytes {0,1}
__device__ __forceinline__ unsigned expand4(unsigned b) {
    return (b & 1u) | ((b & 2u) << 7) | ((b & 4u) << 14) | ((b & 8u) << 21);
}

// ---------------------------------------------------------------------------
// scales: per-column pow2 scales
// ---------------------------------------------------------------------------
__global__ void k_scale1(const float* __restrict__ Wh) {
    int n = blockIdx.x * blockDim.x + threadIdx.x;   // 0..1023
    float m = 0.f;
    for (int k = 0; k < 256; k++) m = fmaxf(m, fabsf(Wh[k * HH + n]));
    int e = (m > 0.f) ? (ilogbf(m) + 1) : 0;
    g_qf1[n]  = ldexpf(1.f, 22 - e);
    g_cmb1[n] = ldexpf(1.f, e - 22);
}
__global__ void k_scale2(const float* __restrict__ Wo) {
    int n = threadIdx.x;
    if (n >= 16) return;
    float m = 0.f;
    if (n < CC) for (int k = 0; k < HH; k++) m = fmaxf(m, fabsf(Wo[k * CC + n]));
    int e = (m > 0.f) ? (ilogbf(m) + 1) : 0;
    g_qf2[n]  = ldexpf(1.f, 30 - e);
    g_cmb2[n] = ldexpf(1.f, e - 30);
}

// hidden W -> 3 balanced base-256 digit planes (23-bit quant), packed 4 k/word
__global__ void k_quantb(const float* __restrict__ Wh) {
    int gid = blockIdx.x * blockDim.x + threadIdx.x;  // 65536 = 64kq * 1024h
    int kq = gid >> 10, h = gid & 1023;
    float qf = g_qf1[h];
    unsigned wp[3] = {0, 0, 0};
#pragma unroll
    for (int j = 0; j < 4; j++) {
        int q = __float2int_rn(Wh[(4 * kq + j) * HH + h] * qf);
        int d0 = ((q + 128) & 255) - 128; q = (q - d0) >> 8;
        int d1 = ((q + 128) & 255) - 128; q = (q - d1) >> 8;   // |q| <= 66
        wp[0] |= ((unsigned)d0 & 255u) << (8 * j);
        wp[1] |= ((unsigned)d1 & 255u) << (8 * j);
        wp[2] |= ((unsigned)q  & 255u) << (8 * j);
    }
#pragma unroll
    for (int p = 0; p < 3; p++) g_Bq1[(p * 64 + kq) * HH + h] = wp[p];
}

__global__ void k_quant2(const float* __restrict__ Wo) {
    int gid = blockIdx.x * blockDim.x + threadIdx.x;  // 4096 = 256kq * 16n
    int kq = gid >> 4, n = gid & 15;
    float qf = g_qf2[n];
    unsigned wp[4] = {0, 0, 0, 0};
#pragma unroll
    for (int j = 0; j < 4; j++) {
        float w = (n < CC) ? Wo[(4 * kq + j) * CC + n] : 0.f;
        int q = __float2int_rn(w * qf);
#pragma unroll
        for (int p = 0; p < 4; p++) {
            int di = ((q + 128) & 255) - 128;
            wp[p] |= ((unsigned)di & 255u) << (8 * j);
            q = (q - di) >> 8;
        }
    }
#pragma unroll
    for (int p = 0; p < 4; p++) g_Bq2[(p * 256 + kq) * 16 + n] = wp[p];
}

// ---------------------------------------------------------------------------
// encoder: IF neuron, soft reset; exact fp32 matching reference op order.
// ---------------------------------------------------------------------------
__global__ void __launch_bounds__(128, 8) k_encoder(const float* __restrict__ x) {
    int b = blockIdx.x, j = threadIdx.x;
    const float* xp = x + (size_t)b * TT * ORDER + j;
    unsigned* wp = g_se_bits + (size_t)b * TT * 8 + (j >> 5);
    float vp = 0.f, vn = 0.f;
#pragma unroll 4
    for (int t = 0; t < TT; t++) {
        float val = xp[(size_t)t * ORDER];
        vp = __fadd_rn(vp, fmaxf(val, 0.f));
        bool sp = (vp >= 1.0f);
        unsigned mp = __ballot_sync(0xffffffffu, sp);
        if (sp) vp = __fsub_rn(vp, 1.0f);
        vn = __fadd_rn(vn, fmaxf(-val, 0.f));
        bool sn = (vn >= 1.0f);
        unsigned mn = __ballot_sync(0xffffffffu, sn);
        if (sn) vn = __fsub_rn(vn, 1.0f);
        if ((j & 31) == 0) { wp[t * 8] = mp; wp[t * 8 + 4] = mn; }
    }
}

// ---------------------------------------------------------------------------
// fused hidden layer: exact limb GEMM (planes 0,1 on tensor pipe via IMMA;
// plane 2 on fma pipe via dp4a, interleaved) + in-smem LIF scan.
// CTA = (ntile 64 h-cols, b). 8 serial t-tiles of 128 rows.
// smem words: A s8 [0,8704) stride 68w | I [8704,17408) stride 68w |
//             B [17408,31232) 3p x 64kq x 72w-stride | cmb [31232,31296)
// ---------------------------------------------------------------------------
#define SM_AW 0
#define SM_IW 8704
#define SM_BW 17408
#define SM_CW 31232
#define SMEM1 (31296 * 4)

__device__ __forceinline__ void build_A(int* sm, int b, int tbase,
                                        int tid0, int nthr) {
    for (int i = tid0; i < 1024; i += nthr) {
        int r = i >> 3, g = i & 7;
        unsigned bits = g_se_bits[(size_t)(b * TT + tbase + r) * 8 + g];
        char* dst = (char*)(sm + SM_AW) + r * 272 + g * 32;
        uint4 u;
        u.x = expand4(bits);       u.y = expand4(bits >> 4);
        u.z = expand4(bits >> 8);  u.w = expand4(bits >> 12);
        *(uint4*)dst = u;
        u.x = expand4(bits >> 16); u.y = expand4(bits >> 20);
        u.z = expand4(bits >> 24); u.w = expand4(bits >> 28);
        *(uint4*)(dst + 16) = u;
    }
}

__global__ void __launch_bounds__(256, 1) k_hidden() {
    extern __shared__ int sm[];
    const int tid = threadIdx.x, lane = tid & 31, warp = tid >> 5;
    const int ntile = blockIdx.x, b = blockIdx.y;
    const int wm = warp & 3, wn = warp >> 2;
    const int rowg = tid >> 3, colg = tid & 7;   // dp4a ownership

    // load B slice: 3 planes x 64 kq x 64 cols
    for (int i = tid; i < 12288; i += 256) {
        int p = i >> 12, kq = (i >> 6) & 63, n = i & 63;
        sm[SM_BW + p * 4608 + kq * 72 + n] =
            (int)g_Bq1[(p * 64 + kq) * HH + ntile * 64 + n];
    }
    if (tid < 64) ((float*)(sm + SM_CW))[tid] = g_cmb1[ntile * 64 + tid];

    build_A(sm, b, 0, tid, 256);
    __syncthreads();

    const unsigned Aaddr0 = smaddr(sm + SM_AW)
        + (wm * 32 + (lane & 7) + ((lane >> 3) & 1) * 8) * 272 + (lane >> 4) * 16;
    const unsigned Bsm = smaddr(sm + SM_BW);
    float v = 0.f;   // threads 0..63: LIF state for h = ntile*64 + tid

    for (int mt = 0; mt < 8; mt++) {
        int acc[2][2][4][4];
        int acc2[4][8];
#pragma unroll
        for (int p = 0; p < 2; p++)
#pragma unroll
            for (int mf = 0; mf < 2; mf++)
#pragma unroll
                for (int nf = 0; nf < 4; nf++)
#pragma unroll
                    for (int r = 0; r < 4; r++) acc[p][mf][nf][r] = 0;
#pragma unroll
        for (int i = 0; i < 4; i++)
#pragma unroll
            for (int j = 0; j < 8; j++) acc2[i][j] = 0;

#pragma unroll 1
        for (int ks = 0; ks < 8; ks++) {
            unsigned a0[4], a1[4];
            ldmx4(a0, Aaddr0 + ks * 32);
            ldmx4(a1, Aaddr0 + 16 * 272 + ks * 32);
#pragma unroll
            for (int p = 0; p < 2; p++) {
                unsigned ba = Bsm
                    + (p * 4608 + (ks * 8 + (lane & 3)) * 72 + wn * 32 + (lane >> 2)) * 4;
#pragma unroll
                for (int nf = 0; nf < 4; nf++) {
                    unsigned b0 = lds32(ba + nf * 32);
                    unsigned b1 = lds32(ba + 1152 + nf * 32);
                    imma16832(acc[p][0][nf], a0, b0, b1);
                    imma16832(acc[p][1][nf], a1, b0, b1);
                }
            }
            // plane 2 on the fma pipe: kq = ks*8 .. ks*8+7
#pragma unroll 2
            for (int kk = 0; kk < 8; kk++) {
                int kq = ks * 8 + kk;
                int Aw[4], Bw[8];
#pragma unroll
                for (int i = 0; i < 4; i++)
                    Aw[i] = sm[SM_AW + (rowg * 4 + i) * 68 + kq];
#pragma unroll
                for (int j = 0; j < 8; j++)
                    Bw[j] = sm[SM_BW + 9216 + kq * 72 + colg * 8 + j];
#pragma unroll
                for (int i = 0; i < 4; i++)
#pragma unroll
                    for (int j = 0; j < 8; j++)
                        acc2[i][j] = __dp4a(Aw[i], Bw[j], acc2[i][j]);
            }
        }

        // dp4a partials -> smem (int)
#pragma unroll
        for (int i = 0; i < 4; i++)
#pragma unroll
            for (int j = 0; j < 8; j++)
                sm[SM_IW + (rowg * 4 + i) * 68 + colg * 8 + j] = acc2[i][j];
        __syncthreads();

        // combine limbs (exact ints, one fp rounding) -> smem I (float)
        const float* cmb = (const float*)(sm + SM_CW);
#pragma unroll
        for (int mf = 0; mf < 2; mf++) {
            int rl = wm * 32 + mf * 16 + (lane >> 2);
#pragma unroll
            for (int nf = 0; nf < 4; nf++) {
                int cl = wn * 32 + nf * 8 + (lane & 3) * 2;
                float c0 = cmb[cl], c1 = cmb[cl + 1];
                int* I0 = sm + SM_IW + rl * 68 + cl;
                int* I1 = sm + SM_IW + (rl + 8) * 68 + cl;
                float v0 = fmaf(65536.f, (float)I0[0],
                    (float)(acc[0][mf][nf][0] + (acc[1][mf][nf][0] << 8))) * c0;
                float v1 = fmaf(65536.f, (float)I0[1],
                    (float)(acc[0][mf][nf][1] + (acc[1][mf][nf][1] << 8))) * c1;
                float v2 = fmaf(65536.f, (float)I1[0],
                    (float)(acc[0][mf][nf][2] + (acc[1][mf][nf][2] << 8))) * c0;
                float v3 = fmaf(65536.f, (float)I1[1],
                    (float)(acc[0][mf][nf][3] + (acc[1][mf][nf][3] << 8))) * c1;
                ((float*)I0)[0] = v0; ((float*)I0)[1] = v1;
                ((float*)I1)[0] = v2; ((float*)I1)[1] = v3;
            }
        }
        __syncthreads();

        if (tid < 64) {
            // LIF scan over this tile's 128 timesteps
            const float* Ic = (const float*)(sm + SM_IW) + tid;
            unsigned* ow = g_sh_bits + (size_t)(b * TT + mt * 128) * 32
                         + ntile * 2 + (tid >> 5);
#pragma unroll 4
            for (int tl = 0; tl < 128; tl++) {
                float I = Ic[tl * 68];
                v = __fadd_rn(__fmul_rn(0.9f, v), I);
                bool s = (v >= 1.0f);
                unsigned m = __ballot_sync(0xffffffffu, s);
                if (s) v = __fsub_rn(v, 1.0f);
                if ((tid & 31) == 0) ow[(size_t)tl * 32] = m;
            }
        } else if (mt < 7) {
            // overlap: build next A tile with the other 192 threads
            build_A(sm, b, (mt + 1) * 128, tid - 64, 192);
        }
        __syncthreads();
    }
}

// ---------------------------------------------------------------------------
// GEMM2 (exact int8 limbs): I2 = s_h @ W_otp, N padded 16. (proven R3 path)
// ---------------------------------------------------------------------------
#define SMEM2 (98304 + 16896 + 64)
__global__ void __launch_bounds__(256, 1) k_gemm2() {
    extern __shared__ unsigned smu[];
    unsigned* smB = smu;           // 4p x 256kq x (24-stride, 16 n) words
    unsigned* smb = smu + 24576;   // 128 rows x 33 words spike bits
    float* smC = (float*)(smu + 24576 + 4224);

    const int tid = threadIdx.x, lane = tid & 31, warp = tid >> 5;
    const int mbase = blockIdx.x * 128;

    for (int i = tid; i < 16384; i += 256) {
        int p = i >> 12, kq = (i >> 4) & 255, n = i & 15;
        smB[(p * 256 + kq) * 24 + n] = g_Bq2[i];
    }
    for (int i = tid; i < 4096; i += 256)
        smb[(i >> 5) * 33 + (i & 31)] = g_sh_bits[(size_t)(mbase + (i >> 5)) * 32 + (i & 31)];
    if (tid < 16) smC[tid] = g_cmb2[tid];
    __syncthreads();

    int acc[4][2][4];
#pragma unroll
    for (int p = 0; p < 4; p++)
#pragma unroll
        for (int nf = 0; nf < 2; nf++)
#pragma unroll
            for (int r = 0; r < 4; r++) acc[p][nf][r] = 0;

    const int r0 = warp * 16 + (lane >> 2);
    const int sh = 4 * (lane & 3);
    const unsigned Bsm = smaddr(smB);

#pragma unroll 4
    for (int ks = 0; ks < 32; ks++) {
        unsigned w0 = smb[r0 * 33 + ks];
        unsigned w1 = smb[(r0 + 8) * 33 + ks];
        unsigned a[4];
        a[0] = expand4(w0 >> sh);
        a[1] = expand4(w1 >> sh);
        a[2] = expand4(w0 >> (16 + sh));
        a[3] = expand4(w1 >> (16 + sh));
#pragma unroll
        for (int p = 0; p < 4; p++) {
            unsigned ba = Bsm + ((p * 256 + ks * 8 + (lane & 3)) * 24 + (lane >> 2)) * 4;
#pragma unroll
            for (int nf = 0; nf < 2; nf++) {
                unsigned b0 = lds32(ba + nf * 32);
                unsigned b1 = lds32(ba + 384 + nf * 32);
                imma16832(acc[p][nf], a, b0, b1);
            }
        }
    }

    int row = mbase + r0;
#pragma unroll
    for (int nf = 0; nf < 2; nf++) {
        int cl = nf * 8 + (lane & 3) * 2;
        if (cl < CC) {
            float c0 = smC[cl], c1 = smC[cl + 1];
            float v0 = ((float)(acc[0][nf][0] + (acc[1][nf][0] << 8))
                + 65536.f * (float)(acc[2][nf][0] + (acc[3][nf][0] << 8))) * c0;
            float v1 = ((float)(acc[0][nf][1] + (acc[1][nf][1] << 8))
                + 65536.f * (float)(acc[2][nf][1] + (acc[3][nf][1] << 8))) * c1;
            float v2 = ((float)(acc[0][nf][2] + (acc[1][nf][2] << 8))
                + 65536.f * (float)(acc[2][nf][2] + (acc[3][nf][2] << 8))) * c0;
            float v3 = ((float)(acc[0][nf][3] + (acc[1][nf][3] << 8))
                + 65536.f * (float)(acc[2][nf][3] + (acc[3][nf][3] << 8))) * c1;
            *(float2*)(g_I2 + (size_t)row * CC + cl) = make_float2(v0, v1);
            *(float2*)(g_I2 + (size_t)(row + 8) * CC + cl) = make_float2(v2, v3);
        }
    }
}

// ---------------------------------------------------------------------------
// scan2: leaky integrator per (b,c); emits membrane potential each step.
// ---------------------------------------------------------------------------
__global__ void k_scan2(float* __restrict__ out) {
    int b = blockIdx.x, c = threadIdx.x;
    if (c >= CC) return;
    const float* p = g_I2 + (size_t)b * TT * CC + c;
    float* q = out + (size_t)b * TT * CC + c;
    float v = 0.f;
#pragma unroll 4
    for (int t = 0; t < TT; t++) {
        v = __fadd_rn(__fmul_rn(0.9f, v), p[(size_t)t * CC]);
        q[(size_t)t * CC] = v;
    }
}

// ---------------------------------------------------------------------------
extern "C" void kernel_launch(void* const* d_in, const int* in_sizes, int n_in,
                              void* d_out, int out_size) {
    const float* x  = (const float*)d_in[0];
    const float* Wh = (const float*)d_in[1];
    const float* Wo = (const float*)d_in[2];
    float* out = (float*)d_out;

    cudaFuncSetAttribute(k_hidden, cudaFuncAttributeMaxDynamicSharedMemorySize, SMEM1);
    cudaFuncSetAttribute(k_gemm2, cudaFuncAttributeMaxDynamicSharedMemorySize, SMEM2);

    // order chosen so the heavy fused kernel sits in the ncu capture slot
    k_scale1<<<4, 256>>>(Wh);
    k_quantb<<<256, 256>>>(Wh);
    k_encoder<<<BB, 128>>>(x);
    k_hidden<<<dim3(16, BB), 256, SMEM1>>>();
    k_scale2<<<1, 32>>>(Wo);
    k_quant2<<<16, 256>>>(Wo);
    k_gemm2<<<4096, 256, SMEM2>>>();
    k_scan2<<<BB, 32>>>(out);
}

// round 6
// speedup vs baseline: 1.5878x; 1.2723x over previous
#include <cuda_runtime.h>
#include <cstdint>

#define BB 512
#define TT 1024
#define ORDER 128
#define HH 1024
#define CC 10
#define NROWS (BB*TT)   // 524288

// ---- device scratch (module-load, not runtime allocs) ----
__device__ unsigned g_se_bits[(size_t)NROWS * 8];    // 16 MB encoder spikes
__device__ unsigned g_sh_bits[(size_t)NROWS * 32];   // 64 MB hidden spikes
__device__ float    g_I2[(size_t)NROWS * CC];        // 21 MB output currents
__device__ unsigned g_Bq1[3 * 64 * HH];              // hidden W digits [p][kq][h] (23-bit)
__device__ unsigned g_Bq2[3 * 256 * 16];             // output W digits [p][kq][n] (23-bit)
__device__ float    g_cmb1[HH], g_qf1[HH];
__device__ float    g_cmb2[16], g_qf2[16];

__device__ __forceinline__ unsigned smaddr(const void* p) {
    return (unsigned)__cvta_generic_to_shared(p);
}
__device__ __forceinline__ unsigned lds32(unsigned a) {
    unsigned v; asm volatile("ld.shared.b32 %0, [%1];" : "=r"(v) : "r"(a)); return v;
}
__device__ __forceinline__ void ldmx4(unsigned a[4], unsigned addr) {
    asm volatile("ldmatrix.sync.aligned.m8n8.x4.shared.b16 {%0,%1,%2,%3}, [%4];"
                 : "=r"(a[0]), "=r"(a[1]), "=r"(a[2]), "=r"(a[3]) : "r"(addr));
}
__device__ __forceinline__ void imma16832(int c[4], const unsigned a[4],
                                          unsigned b0, unsigned b1) {
    asm volatile(
        "mma.sync.aligned.m16n8k32.row.col.s32.s8.s8.s32 "
        "{%0,%1,%2,%3}, {%4,%5,%6,%7}, {%8,%9}, {%0,%1,%2,%3};"
        : "+r"(c[0]), "+r"(c[1]), "+r"(c[2]), "+r"(c[3])
        : "r"(a[0]), "r"(a[1]), "r"(a[2]), "r"(a[3]), "r"(b0), "r"(b1));
}
// 4 spike bits -> 4 s8 bytes {0,1}
__device__ __forceinline__ unsigned expand4(unsigned b) {
    return (b & 1u) | ((b & 2u) << 7) | ((b & 4u) << 14) | ((b & 8u) << 21);
}

// ---------------------------------------------------------------------------
// scales: per-column pow2 scales (23-bit quantization)
// ---------------------------------------------------------------------------
__global__ void k_scale1(const float* __restrict__ Wh) {
    int n = blockIdx.x * blockDim.x + threadIdx.x;   // 0..1023
    float m = 0.f;
    for (int k = 0; k < 256; k++) m = fmaxf(m, fabsf(Wh[k * HH + n]));
    int e = (m > 0.f) ? (ilogbf(m) + 1) : 0;
    g_qf1[n]  = ldexpf(1.f, 22 - e);
    g_cmb1[n] = ldexpf(1.f, e - 22);
}
__global__ void k_scale2(const float* __restrict__ Wo) {
    int n = threadIdx.x;
    if (n >= 16) return;
    float m = 0.f;
    if (n < CC) for (int k = 0; k < HH; k++) m = fmaxf(m, fabsf(Wo[k * CC + n]));
    int e = (m > 0.f) ? (ilogbf(m) + 1) : 0;
    g_qf2[n]  = ldexpf(1.f, 22 - e);
    g_cmb2[n] = ldexpf(1.f, e - 22);
}

// hidden W -> 3 balanced base-256 digit planes (23-bit), packed 4 k/word
__global__ void k_quantb(const float* __restrict__ Wh) {
    int gid = blockIdx.x * blockDim.x + threadIdx.x;  // 65536 = 64kq * 1024h
    int kq = gid >> 10, h = gid & 1023;
    float qf = g_qf1[h];
    unsigned wp[3] = {0, 0, 0};
#pragma unroll
    for (int j = 0; j < 4; j++) {
        int q = __float2int_rn(Wh[(4 * kq + j) * HH + h] * qf);
        int d0 = ((q + 128) & 255) - 128; q = (q - d0) >> 8;
        int d1 = ((q + 128) & 255) - 128; q = (q - d1) >> 8;   // |q| <= 66
        wp[0] |= ((unsigned)d0 & 255u) << (8 * j);
        wp[1] |= ((unsigned)d1 & 255u) << (8 * j);
        wp[2] |= ((unsigned)q  & 255u) << (8 * j);
    }
#pragma unroll
    for (int p = 0; p < 3; p++) g_Bq1[(p * 64 + kq) * HH + h] = wp[p];
}

__global__ void k_quant2(const float* __restrict__ Wo) {
    int gid = blockIdx.x * blockDim.x + threadIdx.x;  // 4096 = 256kq * 16n
    int kq = gid >> 4, n = gid & 15;
    float qf = g_qf2[n];
    unsigned wp[3] = {0, 0, 0};
#pragma unroll
    for (int j = 0; j < 4; j++) {
        float w = (n < CC) ? Wo[(4 * kq + j) * CC + n] : 0.f;
        int q = __float2int_rn(w * qf);
        int d0 = ((q + 128) & 255) - 128; q = (q - d0) >> 8;
        int d1 = ((q + 128) & 255) - 128; q = (q - d1) >> 8;   // |q| <= 66
        wp[0] |= ((unsigned)d0 & 255u) << (8 * j);
        wp[1] |= ((unsigned)d1 & 255u) << (8 * j);
        wp[2] |= ((unsigned)q  & 255u) << (8 * j);
    }
#pragma unroll
    for (int p = 0; p < 3; p++) g_Bq2[(p * 256 + kq) * 16 + n] = wp[p];
}

// ---------------------------------------------------------------------------
// encoder: IF neuron, soft reset; exact fp32 matching reference op order.
// ---------------------------------------------------------------------------
__global__ void __launch_bounds__(128, 8) k_encoder(const float* __restrict__ x) {
    int b = blockIdx.x, j = threadIdx.x;
    const float* xp = x + (size_t)b * TT * ORDER + j;
    unsigned* wp = g_se_bits + (size_t)b * TT * 8 + (j >> 5);
    float vp = 0.f, vn = 0.f;
#pragma unroll 4
    for (int t = 0; t < TT; t++) {
        float val = xp[(size_t)t * ORDER];
        vp = __fadd_rn(vp, fmaxf(val, 0.f));
        bool sp = (vp >= 1.0f);
        unsigned mp = __ballot_sync(0xffffffffu, sp);
        if (sp) vp = __fsub_rn(vp, 1.0f);
        vn = __fadd_rn(vn, fmaxf(-val, 0.f));
        bool sn = (vn >= 1.0f);
        unsigned mn = __ballot_sync(0xffffffffu, sn);
        if (sn) vn = __fsub_rn(vn, 1.0f);
        if ((j & 31) == 0) { wp[t * 8] = mp; wp[t * 8 + 4] = mn; }
    }
}

// ---------------------------------------------------------------------------
// fused hidden layer v2: balanced pipes + 2 CTAs/SM.
//   tensor pipe: plane0 (all kq) + plane1 (kq 0..31)
//   fma pipe (dp4a): plane1 (kq 32..63) + plane2 (all kq)
// CTA = (ntile of 32 h-cols, b). 8 serial t-tiles of 128 rows, LIF fused.
// smem words: A s8 [0,8704) stride 68 | I [8704,13312) stride 36 |
//             B [13312,20992) 3p x 64kq x 40w | cmb [20992,21024)
// ---------------------------------------------------------------------------
#define SM_AW 0
#define SM_IW 8704
#define SM_BW 13312
#define SM_CW 20992
#define SMEM1 (21024 * 4)

__device__ __forceinline__ void build_A(int* sm, int b, int tbase,
                                        int tid0, int nthr) {
    for (int i = tid0; i < 1024; i += nthr) {
        int r = i >> 3, g = i & 7;
        unsigned bits = g_se_bits[(size_t)(b * TT + tbase + r) * 8 + g];
        char* dst = (char*)(sm + SM_AW) + r * 272 + g * 32;
        uint4 u;
        u.x = expand4(bits);       u.y = expand4(bits >> 4);
        u.z = expand4(bits >> 8);  u.w = expand4(bits >> 12);
        *(uint4*)dst = u;
        u.x = expand4(bits >> 16); u.y = expand4(bits >> 20);
        u.z = expand4(bits >> 24); u.w = expand4(bits >> 28);
        *(uint4*)(dst + 16) = u;
    }
}

__global__ void __launch_bounds__(256, 2) k_hidden() {
    extern __shared__ int sm[];
    const int tid = threadIdx.x, lane = tid & 31, warp = tid >> 5;
    const int ntile = blockIdx.x, b = blockIdx.y;
    const int wm = warp & 3, wn = warp >> 2;        // 4 x 2 warp grid
    const int rowg = tid >> 3, colg = tid & 7;      // dp4a ownership (4r x 4c)

    // load B slice: 3 planes x 64 kq x 32 cols (stride 40 words)
    for (int i = tid; i < 6144; i += 256) {
        int p = i >> 11, kq = (i >> 5) & 63, n = i & 31;
        sm[SM_BW + p * 2560 + kq * 40 + n] =
            (int)g_Bq1[(p * 64 + kq) * HH + ntile * 32 + n];
    }
    if (tid < 32) ((float*)(sm + SM_CW))[tid] = g_cmb1[ntile * 32 + tid];

    build_A(sm, b, 0, tid, 256);
    __syncthreads();

    const unsigned Aaddr0 = smaddr(sm + SM_AW)
        + (wm * 32 + (lane & 7) + ((lane >> 3) & 1) * 8) * 272 + (lane >> 4) * 16;
    const unsigned Bsm = smaddr(sm + SM_BW);
    float v = 0.f;   // threads 0..31: LIF state for h = ntile*32 + tid

    for (int mt = 0; mt < 8; mt++) {
        int accT[2][2][2][4];    // tensor: [plane][mf][nf][r]
        int acc1[4][4], acc2[4][4];
#pragma unroll
        for (int p = 0; p < 2; p++)
#pragma unroll
            for (int mf = 0; mf < 2; mf++)
#pragma unroll
                for (int nf = 0; nf < 2; nf++)
#pragma unroll
                    for (int r = 0; r < 4; r++) accT[p][mf][nf][r] = 0;
#pragma unroll
        for (int i = 0; i < 4; i++)
#pragma unroll
            for (int j = 0; j < 4; j++) { acc1[i][j] = 0; acc2[i][j] = 0; }

#pragma unroll 1
        for (int ks = 0; ks < 8; ks++) {
            unsigned a0[4], a1[4];
            ldmx4(a0, Aaddr0 + ks * 32);
            ldmx4(a1, Aaddr0 + 16 * 272 + ks * 32);
            // plane0 on tensor (all ks)
            {
                unsigned ba = Bsm
                    + ((ks * 8 + (lane & 3)) * 40 + wn * 16 + (lane >> 2)) * 4;
#pragma unroll
                for (int nf = 0; nf < 2; nf++) {
                    unsigned b0 = lds32(ba + nf * 32);
                    unsigned b1 = lds32(ba + 640 + nf * 32);   // kq+4
                    imma16832(accT[0][0][nf], a0, b0, b1);
                    imma16832(accT[0][1][nf], a1, b0, b1);
                }
            }
            // plane1 first half (kq 0..31) on tensor
            if (ks < 4) {
                unsigned ba = Bsm
                    + (2560 + (ks * 8 + (lane & 3)) * 40 + wn * 16 + (lane >> 2)) * 4;
#pragma unroll
                for (int nf = 0; nf < 2; nf++) {
                    unsigned b0 = lds32(ba + nf * 32);
                    unsigned b1 = lds32(ba + 640 + nf * 32);
                    imma16832(accT[1][0][nf], a0, b0, b1);
                    imma16832(accT[1][1][nf], a1, b0, b1);
                }
            }
            // fma pipe: plane2 (all) + plane1 second half (ks>=4)
#pragma unroll 2
            for (int kk = 0; kk < 8; kk++) {
                int kq = ks * 8 + kk;
                int Aw[4], Bw[4];
#pragma unroll
                for (int i = 0; i < 4; i++)
                    Aw[i] = sm[SM_AW + (rowg * 4 + i) * 68 + kq];
#pragma unroll
                for (int j = 0; j < 4; j++)
                    Bw[j] = sm[SM_BW + 5120 + kq * 40 + colg * 4 + j];
#pragma unroll
                for (int i = 0; i < 4; i++)
#pragma unroll
                    for (int j = 0; j < 4; j++)
                        acc2[i][j] = __dp4a(Aw[i], Bw[j], acc2[i][j]);
                if (ks >= 4) {
#pragma unroll
                    for (int j = 0; j < 4; j++)
                        Bw[j] = sm[SM_BW + 2560 + kq * 40 + colg * 4 + j];
#pragma unroll
                    for (int i = 0; i < 4; i++)
#pragma unroll
                        for (int j = 0; j < 4; j++)
                            acc1[i][j] = __dp4a(Aw[i], Bw[j], acc1[i][j]);
                }
            }
        }

        // dp4a partials -> smem: s = p1b + 256*p2 (exact int32)
#pragma unroll
        for (int i = 0; i < 4; i++)
#pragma unroll
            for (int j = 0; j < 4; j++)
                sm[SM_IW + (rowg * 4 + i) * 36 + colg * 4 + j] =
                    acc1[i][j] + acc2[i][j] * 256;
        __syncthreads();

        // combine: I = (p0 + 256*p1a) + 256*s, one fp32 rounding, * cmb
        const float* cmb = (const float*)(sm + SM_CW);
#pragma unroll
        for (int mf = 0; mf < 2; mf++) {
            int rl = wm * 32 + mf * 16 + (lane >> 2);
#pragma unroll
            for (int nf = 0; nf < 2; nf++) {
                int cl = wn * 16 + nf * 8 + (lane & 3) * 2;
#pragma unroll
                for (int r = 0; r < 4; r++) {
                    int row = rl + (r >> 1) * 8;
                    int col = cl + (r & 1);
                    int* slot = sm + SM_IW + row * 36 + col;
                    int tot = accT[0][mf][nf][r] + (accT[1][mf][nf][r] << 8)
                            + slot[0] * 256;
                    *(float*)slot = (float)tot * cmb[col];
                }
            }
        }
        __syncthreads();

        if (warp == 0) {
            // LIF scan over this tile's 128 timesteps (32 h per CTA)
            const float* Ic = (const float*)(sm + SM_IW) + tid;
            unsigned* ow = g_sh_bits + (size_t)(b * TT + mt * 128) * 32 + ntile;
#pragma unroll 4
            for (int tl = 0; tl < 128; tl++) {
                float I = Ic[tl * 36];
                v = __fadd_rn(__fmul_rn(0.9f, v), I);
                bool s = (v >= 1.0f);
                unsigned m = __ballot_sync(0xffffffffu, s);
                if (s) v = __fsub_rn(v, 1.0f);
                if (lane == 0) ow[(size_t)tl * 32] = m;
            }
        } else if (mt < 7) {
            build_A(sm, b, (mt + 1) * 128, tid - 32, 224);
        }
        __syncthreads();
    }
}

// ---------------------------------------------------------------------------
// GEMM2 (exact, 3 int8 limb planes): I2 = s_h @ W_otp, N padded 16.
// ---------------------------------------------------------------------------
#define SMEM2 ((18432 + 4224 + 16) * 4)
__global__ void __launch_bounds__(256, 1) k_gemm2() {
    extern __shared__ unsigned smu[];
    unsigned* smB = smu;           // 3p x 256kq x (24-stride, 16 n) words
    unsigned* smb = smu + 18432;   // 128 rows x 33 words spike bits
    float* smC = (float*)(smu + 18432 + 4224);

    const int tid = threadIdx.x, lane = tid & 31, warp = tid >> 5;
    const int mbase = blockIdx.x * 128;

    for (int i = tid; i < 12288; i += 256) {
        int p = i >> 12, kq = (i >> 4) & 255, n = i & 15;
        smB[(p * 256 + kq) * 24 + n] = g_Bq2[i];
    }
    for (int i = tid; i < 4096; i += 256)
        smb[(i >> 5) * 33 + (i & 31)] = g_sh_bits[(size_t)(mbase + (i >> 5)) * 32 + (i & 31)];
    if (tid < 16) smC[tid] = g_cmb2[tid];
    __syncthreads();

    int acc[3][2][4];
#pragma unroll
    for (int p = 0; p < 3; p++)
#pragma unroll
        for (int nf = 0; nf < 2; nf++)
#pragma unroll
            for (int r = 0; r < 4; r++) acc[p][nf][r] = 0;

    const int r0 = warp * 16 + (lane >> 2);
    const int sh = 4 * (lane & 3);
    const unsigned Bsm = smaddr(smB);

#pragma unroll 4
    for (int ks = 0; ks < 32; ks++) {
        unsigned w0 = smb[r0 * 33 + ks];
        unsigned w1 = smb[(r0 + 8) * 33 + ks];
        unsigned a[4];
        a[0] = expand4(w0 >> sh);
        a[1] = expand4(w1 >> sh);
        a[2] = expand4(w0 >> (16 + sh));
        a[3] = expand4(w1 >> (16 + sh));
#pragma unroll
        for (int p = 0; p < 3; p++) {
            unsigned ba = Bsm + ((p * 256 + ks * 8 + (lane & 3)) * 24 + (lane >> 2)) * 4;
#pragma unroll
            for (int nf = 0; nf < 2; nf++) {
                unsigned b0 = lds32(ba + nf * 32);
                unsigned b1 = lds32(ba + 384 + nf * 32);
                imma16832(acc[p][nf], a, b0, b1);
            }
        }
    }

    int row = mbase + r0;
#pragma unroll
    for (int nf = 0; nf < 2; nf++) {
        int cl = nf * 8 + (lane & 3) * 2;
        if (cl < CC) {
            float c0 = smC[cl], c1 = smC[cl + 1];
            float v0 = ((float)(acc[0][nf][0] + (acc[1][nf][0] << 8))
                + 65536.f * (float)acc[2][nf][0]) * c0;
            float v1 = ((float)(acc[0][nf][1] + (acc[1][nf][1] << 8))
                + 65536.f * (float)acc[2][nf][1]) * c1;
            float v2 = ((float)(acc[0][nf][2] + (acc[1][nf][2] << 8))
                + 65536.f * (float)acc[2][nf][2]) * c0;
            float v3 = ((float)(acc[0][nf][3] + (acc[1][nf][3] << 8))
                + 65536.f * (float)acc[2][nf][3]) * c1;
            *(float2*)(g_I2 + (size_t)row * CC + cl) = make_float2(v0, v1);
            *(float2*)(g_I2 + (size_t)(row + 8) * CC + cl) = make_float2(v2, v3);
        }
    }
}

// ---------------------------------------------------------------------------
// scan2: leaky integrator per (b,c); emits membrane potential each step.
// ---------------------------------------------------------------------------
__global__ void k_scan2(float* __restrict__ out) {
    int b = blockIdx.x, c = threadIdx.x;
    if (c >= CC) return;
    const float* p = g_I2 + (size_t)b * TT * CC + c;
    float* q = out + (size_t)b * TT * CC + c;
    float v = 0.f;
#pragma unroll 4
    for (int t = 0; t < TT; t++) {
        v = __fadd_rn(__fmul_rn(0.9f, v), p[(size_t)t * CC]);
        q[(size_t)t * CC] = v;
    }
}

// ---------------------------------------------------------------------------
extern "C" void kernel_launch(void* const* d_in, const int* in_sizes, int n_in,
                              void* d_out, int out_size) {
    const float* x  = (const float*)d_in[0];
    const float* Wh = (const float*)d_in[1];
    const float* Wo = (const float*)d_in[2];
    float* out = (float*)d_out;

    cudaFuncSetAttribute(k_hidden, cudaFuncAttributeMaxDynamicSharedMemorySize, SMEM1);
    cudaFuncSetAttribute(k_gemm2, cudaFuncAttributeMaxDynamicSharedMemorySize, SMEM2);

    k_scale1<<<4, 256>>>(Wh);
    k_quantb<<<256, 256>>>(Wh);
    k_encoder<<<BB, 128>>>(x);
    k_hidden<<<dim3(32, BB), 256, SMEM1>>>();
    k_scale2<<<1, 32>>>(Wo);
    k_quant2<<<16, 256>>>(Wo);
    k_gemm2<<<4096, 256, SMEM2>>>();
    k_scan2<<<BB, 32>>>(out);
}

// round 7
// speedup vs baseline: 1.7520x; 1.1034x over previous
#include <cuda_runtime.h>
#include <cstdint>

#define BB 512
#define TT 1024
#define ORDER 128
#define HH 1024
#define CC 10
#define NROWS (BB*TT)   // 524288

// ---- device scratch (module-load, not runtime allocs) ----
__device__ unsigned g_se_bits[(size_t)NROWS * 8];    // 16 MB encoder spikes
__device__ unsigned g_sh_bits[(size_t)NROWS * 32];   // 64 MB hidden spikes
__device__ float    g_I2[(size_t)NROWS * CC];        // 21 MB output currents
__device__ unsigned g_Bq1[3 * 64 * HH];              // hidden W digits [p][kq][h] (23-bit)
__device__ unsigned g_Bq2[3 * 256 * 16];             // output W digits [p][kq][n] (23-bit)
__device__ float    g_cmb1[HH], g_qf1[HH];
__device__ float    g_cmb2[16], g_qf2[16];

__device__ __forceinline__ unsigned smaddr(const void* p) {
    return (unsigned)__cvta_generic_to_shared(p);
}
__device__ __forceinline__ unsigned lds32(unsigned a) {
    unsigned v; asm volatile("ld.shared.b32 %0, [%1];" : "=r"(v) : "r"(a)); return v;
}
__device__ __forceinline__ void ldmx4(unsigned a[4], unsigned addr) {
    asm volatile("ldmatrix.sync.aligned.m8n8.x4.shared.b16 {%0,%1,%2,%3}, [%4];"
                 : "=r"(a[0]), "=r"(a[1]), "=r"(a[2]), "=r"(a[3]) : "r"(addr));
}
__device__ __forceinline__ void imma16832(int c[4], const unsigned a[4],
                                          unsigned b0, unsigned b1) {
    asm volatile(
        "mma.sync.aligned.m16n8k32.row.col.s32.s8.s8.s32 "
        "{%0,%1,%2,%3}, {%4,%5,%6,%7}, {%8,%9}, {%0,%1,%2,%3};"
        : "+r"(c[0]), "+r"(c[1]), "+r"(c[2]), "+r"(c[3])
        : "r"(a[0]), "r"(a[1]), "r"(a[2]), "r"(a[3]), "r"(b0), "r"(b1));
}
__device__ __forceinline__ unsigned expand4(unsigned b) {
    return (b & 1u) | ((b & 2u) << 7) | ((b & 4u) << 14) | ((b & 8u) << 21);
}
__device__ __forceinline__ void bar_sync(int id, int cnt) {
    asm volatile("bar.sync %0, %1;" :: "r"(id), "r"(cnt) : "memory");
}
__device__ __forceinline__ void bar_arrive(int id, int cnt) {
    asm volatile("bar.arrive %0, %1;" :: "r"(id), "r"(cnt) : "memory");
}

// ---------------------------------------------------------------------------
// scales + quantization (23-bit, per-column pow2 scales)
// ---------------------------------------------------------------------------
__global__ void k_scale1(const float* __restrict__ Wh) {
    int n = blockIdx.x * blockDim.x + threadIdx.x;
    float m = 0.f;
    for (int k = 0; k < 256; k++) m = fmaxf(m, fabsf(Wh[k * HH + n]));
    int e = (m > 0.f) ? (ilogbf(m) + 1) : 0;
    g_qf1[n]  = ldexpf(1.f, 22 - e);
    g_cmb1[n] = ldexpf(1.f, e - 22);
}
__global__ void k_scale2(const float* __restrict__ Wo) {
    int n = threadIdx.x;
    if (n >= 16) return;
    float m = 0.f;
    if (n < CC) for (int k = 0; k < HH; k++) m = fmaxf(m, fabsf(Wo[k * CC + n]));
    int e = (m > 0.f) ? (ilogbf(m) + 1) : 0;
    g_qf2[n]  = ldexpf(1.f, 22 - e);
    g_cmb2[n] = ldexpf(1.f, e - 22);
}

__global__ void k_quantb(const float* __restrict__ Wh) {
    int gid = blockIdx.x * blockDim.x + threadIdx.x;  // 65536 = 64kq * 1024h
    int kq = gid >> 10, h = gid & 1023;
    float qf = g_qf1[h];
    unsigned wp[3] = {0, 0, 0};
#pragma unroll
    for (int j = 0; j < 4; j++) {
        int q = __float2int_rn(Wh[(4 * kq + j) * HH + h] * qf);
        int d0 = ((q + 128) & 255) - 128; q = (q - d0) >> 8;
        int d1 = ((q + 128) & 255) - 128; q = (q - d1) >> 8;   // |q| <= 66
        wp[0] |= ((unsigned)d0 & 255u) << (8 * j);
        wp[1] |= ((unsigned)d1 & 255u) << (8 * j);
        wp[2] |= ((unsigned)q  & 255u) << (8 * j);
    }
#pragma unroll
    for (int p = 0; p < 3; p++) g_Bq1[(p * 64 + kq) * HH + h] = wp[p];
}

__global__ void k_quant2(const float* __restrict__ Wo) {
    int gid = blockIdx.x * blockDim.x + threadIdx.x;  // 4096 = 256kq * 16n
    int kq = gid >> 4, n = gid & 15;
    float qf = g_qf2[n];
    unsigned wp[3] = {0, 0, 0};
#pragma unroll
    for (int j = 0; j < 4; j++) {
        float w = (n < CC) ? Wo[(4 * kq + j) * CC + n] : 0.f;
        int q = __float2int_rn(w * qf);
        int d0 = ((q + 128) & 255) - 128; q = (q - d0) >> 8;
        int d1 = ((q + 128) & 255) - 128; q = (q - d1) >> 8;
        wp[0] |= ((unsigned)d0 & 255u) << (8 * j);
        wp[1] |= ((unsigned)d1 & 255u) << (8 * j);
        wp[2] |= ((unsigned)q  & 255u) << (8 * j);
    }
#pragma unroll
    for (int p = 0; p < 3; p++) g_Bq2[(p * 256 + kq) * 16 + n] = wp[p];
}

// ---------------------------------------------------------------------------
// encoder: IF neuron, soft reset; exact fp32 matching reference op order.
// ---------------------------------------------------------------------------
__global__ void __launch_bounds__(128, 8) k_encoder(const float* __restrict__ x) {
    int b = blockIdx.x, j = threadIdx.x;
    const float* xp = x + (size_t)b * TT * ORDER + j;
    unsigned* wp = g_se_bits + (size_t)b * TT * 8 + (j >> 5);
    float vp = 0.f, vn = 0.f;
#pragma unroll 4
    for (int t = 0; t < TT; t++) {
        float val = xp[(size_t)t * ORDER];
        vp = __fadd_rn(vp, fmaxf(val, 0.f));
        bool sp = (vp >= 1.0f);
        unsigned mp = __ballot_sync(0xffffffffu, sp);
        if (sp) vp = __fsub_rn(vp, 1.0f);
        vn = __fadd_rn(vn, fmaxf(-val, 0.f));
        bool sn = (vn >= 1.0f);
        unsigned mn = __ballot_sync(0xffffffffu, sn);
        if (sn) vn = __fsub_rn(vn, 1.0f);
        if ((j & 31) == 0) { wp[t * 8] = mp; wp[t * 8 + 4] = mn; }
    }
}

// ---------------------------------------------------------------------------
// fused hidden layer v3: warp-specialized pipeline.
//   288 threads: warps 0-7 = GEMM producers, warp 8 = LIF scan consumer.
//   tensor pipe: plane0 (legacy IMMA). fma pipe: planes 1+2 (dp4a, rt~1).
//   I double-buffered; named barriers full/free decouple scan from MMA.
// smem words: A s8 [0,8704) stride 68 | I0 [8704,13312) stride 36 |
//   I1 [13312,17920) | B [17920,25600) 3p x 64kq x 40w | cmb [25600,25632)
// ---------------------------------------------------------------------------
#define SM_AW 0
#define SM_I0 8704
#define SM_I1 13312
#define SM_BW 17920
#define SM_CW 25600
#define SMEM1 (25632 * 4)

__device__ __forceinline__ void build_A(int* sm, int b, int tbase, int tid) {
    for (int i = tid; i < 1024; i += 256) {
        int r = i >> 3, g = i & 7;
        unsigned bits = g_se_bits[(size_t)(b * TT + tbase + r) * 8 + g];
        char* dst = (char*)(sm + SM_AW) + r * 272 + g * 32;
        uint4 u;
        u.x = expand4(bits);       u.y = expand4(bits >> 4);
        u.z = expand4(bits >> 8);  u.w = expand4(bits >> 12);
        *(uint4*)dst = u;
        u.x = expand4(bits >> 16); u.y = expand4(bits >> 20);
        u.z = expand4(bits >> 24); u.w = expand4(bits >> 28);
        *(uint4*)(dst + 16) = u;
    }
}

__global__ void __launch_bounds__(288, 2) k_hidden() {
    extern __shared__ int sm[];
    const int tid = threadIdx.x, lane = tid & 31;
    const int ntile = blockIdx.x, b = blockIdx.y;

    if (tid < 256) {
        // ================= producers: 8 warps =================
        const int warp = tid >> 5;
        const int wm = warp & 3, wn = warp >> 2;      // 4 x 2 warp grid
        const int rowg = tid >> 3, colg = tid & 7;    // dp4a 4r x 4c tiles

        // B slice: 3 planes x 64 kq x 32 cols (stride 40 words)
        for (int i = tid; i < 6144; i += 256) {
            int p = i >> 11, kq = (i >> 5) & 63, n = i & 31;
            sm[SM_BW + p * 2560 + kq * 40 + n] =
                (int)g_Bq1[(p * 64 + kq) * HH + ntile * 32 + n];
        }
        if (tid < 32) ((float*)(sm + SM_CW))[tid] = g_cmb1[ntile * 32 + tid];

        const unsigned Aaddr0 = smaddr(sm + SM_AW)
            + (wm * 32 + (lane & 7) + ((lane >> 3) & 1) * 8) * 272 + (lane >> 4) * 16;
        const unsigned Bsm = smaddr(sm + SM_BW);

        for (int mt = 0; mt < 8; mt++) {
            const int buf = mt & 1;
            int* Ib = sm + (buf ? SM_I1 : SM_I0);

            build_A(sm, b, mt * 128, tid);
            bar_sync(1, 256);
            if (mt >= 2) bar_sync(4 + buf, 288);   // wait: consumer freed buf

            int accT[2][2][4];
            int acc1[4][4], acc2[4][4];
#pragma unroll
            for (int mf = 0; mf < 2; mf++)
#pragma unroll
                for (int nf = 0; nf < 2; nf++)
#pragma unroll
                    for (int r = 0; r < 4; r++) accT[mf][nf][r] = 0;
#pragma unroll
            for (int i = 0; i < 4; i++)
#pragma unroll
                for (int j = 0; j < 4; j++) { acc1[i][j] = 0; acc2[i][j] = 0; }

#pragma unroll 1
            for (int ks = 0; ks < 8; ks++) {
                // --- plane0 on tensor pipe ---
                unsigned a0[4], a1[4];
                ldmx4(a0, Aaddr0 + ks * 32);
                ldmx4(a1, Aaddr0 + 16 * 272 + ks * 32);
                unsigned ba = Bsm
                    + ((ks * 8 + (lane & 3)) * 40 + wn * 16 + (lane >> 2)) * 4;
#pragma unroll
                for (int nf = 0; nf < 2; nf++) {
                    unsigned b0 = lds32(ba + nf * 32);
                    unsigned b1 = lds32(ba + 640 + nf * 32);   // kq+4
                    imma16832(accT[0][nf], a0, b0, b1);
                    imma16832(accT[1][nf], a1, b0, b1);
                }
                // --- planes 1,2 on fma pipe (dp4a), 2 blocks of 4 kq ---
#pragma unroll
                for (int bb = 0; bb < 2; bb++) {
                    int blk = ks * 2 + bb;
                    int Aw[4][4];
#pragma unroll
                    for (int i = 0; i < 4; i++) {
                        int4 t = *(const int4*)(sm + SM_AW
                            + (rowg * 4 + i) * 68 + blk * 4);
                        Aw[i][0] = t.x; Aw[i][1] = t.y;
                        Aw[i][2] = t.z; Aw[i][3] = t.w;
                    }
#pragma unroll
                    for (int k = 0; k < 4; k++) {
                        const int* brow = sm + SM_BW + (blk * 4 + k) * 40 + colg * 4;
                        int4 b1v = *(const int4*)(brow + 2560);
                        int4 b2v = *(const int4*)(brow + 5120);
#pragma unroll
                        for (int i = 0; i < 4; i++) {
                            acc1[i][0] = __dp4a(Aw[i][k], b1v.x, acc1[i][0]);
                            acc1[i][1] = __dp4a(Aw[i][k], b1v.y, acc1[i][1]);
                            acc1[i][2] = __dp4a(Aw[i][k], b1v.z, acc1[i][2]);
                            acc1[i][3] = __dp4a(Aw[i][k], b1v.w, acc1[i][3]);
                            acc2[i][0] = __dp4a(Aw[i][k], b2v.x, acc2[i][0]);
                            acc2[i][1] = __dp4a(Aw[i][k], b2v.y, acc2[i][1]);
                            acc2[i][2] = __dp4a(Aw[i][k], b2v.z, acc2[i][2]);
                            acc2[i][3] = __dp4a(Aw[i][k], b2v.w, acc2[i][3]);
                        }
                    }
                }
            }

            // dp4a partials -> I buffer as ints: s = p1 + 256*p2 (exact)
#pragma unroll
            for (int i = 0; i < 4; i++) {
                int4 s;
                s.x = acc1[i][0] + acc2[i][0] * 256;
                s.y = acc1[i][1] + acc2[i][1] * 256;
                s.z = acc1[i][2] + acc2[i][2] * 256;
                s.w = acc1[i][3] + acc2[i][3] * 256;
                *(int4*)(Ib + (rowg * 4 + i) * 36 + colg * 4) = s;
            }
            bar_sync(1, 256);

            // combine: I = p0 + 256*s, single fp32 rounding, * cmb
            const float* cmb = (const float*)(sm + SM_CW);
#pragma unroll
            for (int mf = 0; mf < 2; mf++) {
#pragma unroll
                for (int nf = 0; nf < 2; nf++) {
#pragma unroll
                    for (int r = 0; r < 4; r++) {
                        int row = wm * 32 + mf * 16 + (lane >> 2) + (r >> 1) * 8;
                        int col = wn * 16 + nf * 8 + (lane & 3) * 2 + (r & 1);
                        int* slot = Ib + row * 36 + col;
                        int tot = accT[mf][nf][r] + slot[0] * 256;
                        *(float*)slot = (float)tot * cmb[col];
                    }
                }
            }
            asm volatile("membar.cta;" ::: "memory");
            bar_arrive(2 + buf, 288);   // signal: buf full
        }
    } else {
        // ================= consumer: LIF scan warp =================
        const int hl = tid - 256;      // 0..31, h = ntile*32 + hl
        float v = 0.f;
        for (int mt = 0; mt < 8; mt++) {
            const int buf = mt & 1;
            bar_sync(2 + buf, 288);    // wait: buf full
            const float* Ic = (const float*)(sm + (buf ? SM_I1 : SM_I0)) + hl;
            unsigned* ow = g_sh_bits + (size_t)(b * TT + mt * 128) * 32 + ntile;
#pragma unroll 4
            for (int tl = 0; tl < 128; tl++) {
                float I = Ic[tl * 36];
                v = __fadd_rn(__fmul_rn(0.9f, v), I);
                bool s = (v >= 1.0f);
                unsigned m = __ballot_sync(0xffffffffu, s);
                if (s) v = __fsub_rn(v, 1.0f);
                if (hl == 0) ow[(size_t)tl * 32] = m;
            }
            bar_arrive(4 + buf, 288);  // signal: buf free
        }
    }
}

// ---------------------------------------------------------------------------
// GEMM2 (exact, 3 int8 limb planes): I2 = s_h @ W_otp, N padded 16.
// ---------------------------------------------------------------------------
#define SMEM2 ((18432 + 4224 + 16) * 4)
__global__ void __launch_bounds__(256, 1) k_gemm2() {
    extern __shared__ unsigned smu[];
    unsigned* smB = smu;           // 3p x 256kq x (24-stride, 16 n) words
    unsigned* smb = smu + 18432;   // 128 rows x 33 words spike bits
    float* smC = (float*)(smu + 18432 + 4224);

    const int tid = threadIdx.x, lane = tid & 31, warp = tid >> 5;
    const int mbase = blockIdx.x * 128;

    for (int i = tid; i < 12288; i += 256) {
        int p = i >> 12, kq = (i >> 4) & 255, n = i & 15;
        smB[(p * 256 + kq) * 24 + n] = g_Bq2[i];
    }
    for (int i = tid; i < 4096; i += 256)
        smb[(i >> 5) * 33 + (i & 31)] = g_sh_bits[(size_t)(mbase + (i >> 5)) * 32 + (i & 31)];
    if (tid < 16) smC[tid] = g_cmb2[tid];
    __syncthreads();

    int acc[3][2][4];
#pragma unroll
    for (int p = 0; p < 3; p++)
#pragma unroll
        for (int nf = 0; nf < 2; nf++)
#pragma unroll
            for (int r = 0; r < 4; r++) acc[p][nf][r] = 0;

    const int r0 = warp * 16 + (lane >> 2);
    const int sh = 4 * (lane & 3);
    const unsigned Bsm = smaddr(smB);

#pragma unroll 4
    for (int ks = 0; ks < 32; ks++) {
        unsigned w0 = smb[r0 * 33 + ks];
        unsigned w1 = smb[(r0 + 8) * 33 + ks];
        unsigned a[4];
        a[0] = expand4(w0 >> sh);
        a[1] = expand4(w1 >> sh);
        a[2] = expand4(w0 >> (16 + sh));
        a[3] = expand4(w1 >> (16 + sh));
#pragma unroll
        for (int p = 0; p < 3; p++) {
            unsigned ba = Bsm + ((p * 256 + ks * 8 + (lane & 3)) * 24 + (lane >> 2)) * 4;
#pragma unroll
            for (int nf = 0; nf < 2; nf++) {
                unsigned b0 = lds32(ba + nf * 32);
                unsigned b1 = lds32(ba + 384 + nf * 32);
                imma16832(acc[p][nf], a, b0, b1);
            }
        }
    }

    int row = mbase + r0;
#pragma unroll
    for (int nf = 0; nf < 2; nf++) {
        int cl = nf * 8 + (lane & 3) * 2;
        if (cl < CC) {
            float c0 = smC[cl], c1 = smC[cl + 1];
            float v0 = ((float)(acc[0][nf][0] + (acc[1][nf][0] << 8))
                + 65536.f * (float)acc[2][nf][0]) * c0;
            float v1 = ((float)(acc[0][nf][1] + (acc[1][nf][1] << 8))
                + 65536.f * (float)acc[2][nf][1]) * c1;
            float v2 = ((float)(acc[0][nf][2] + (acc[1][nf][2] << 8))
                + 65536.f * (float)acc[2][nf][2]) * c0;
            float v3 = ((float)(acc[0][nf][3] + (acc[1][nf][3] << 8))
                + 65536.f * (float)acc[2][nf][3]) * c1;
            *(float2*)(g_I2 + (size_t)row * CC + cl) = make_float2(v0, v1);
            *(float2*)(g_I2 + (size_t)(row + 8) * CC + cl) = make_float2(v2, v3);
        }
    }
}

// ---------------------------------------------------------------------------
// scan2: leaky integrator per (b,c); emits membrane potential each step.
// ---------------------------------------------------------------------------
__global__ void k_scan2(float* __restrict__ out) {
    int b = blockIdx.x, c = threadIdx.x;
    if (c >= CC) return;
    const float* p = g_I2 + (size_t)b * TT * CC + c;
    float* q = out + (size_t)b * TT * CC + c;
    float v = 0.f;
#pragma unroll 4
    for (int t = 0; t < TT; t++) {
        v = __fadd_rn(__fmul_rn(0.9f, v), p[(size_t)t * CC]);
        q[(size_t)t * CC] = v;
    }
}

// ---------------------------------------------------------------------------
extern "C" void kernel_launch(void* const* d_in, const int* in_sizes, int n_in,
                              void* d_out, int out_size) {
    const float* x  = (const float*)d_in[0];
    const float* Wh = (const float*)d_in[1];
    const float* Wo = (const float*)d_in[2];
    float* out = (float*)d_out;

    cudaFuncSetAttribute(k_hidden, cudaFuncAttributeMaxDynamicSharedMemorySize, SMEM1);
    cudaFuncSetAttribute(k_gemm2, cudaFuncAttributeMaxDynamicSharedMemorySize, SMEM2);

    k_scale1<<<4, 256>>>(Wh);
    k_quantb<<<256, 256>>>(Wh);
    k_encoder<<<BB, 128>>>(x);
    k_hidden<<<dim3(32, BB), 288, SMEM1>>>();
    k_scale2<<<1, 32>>>(Wo);
    k_quant2<<<16, 256>>>(Wo);
    k_gemm2<<<4096, 256, SMEM2>>>();
    k_scan2<<<BB, 32>>>(out);
}